// round 7
// baseline (speedup 1.0000x reference)
#include <cuda_runtime.h>
#include <cuda_bf16.h>
#include <stdint.h>

#define NN 8192
#define DD 512
#define LOGIT_SCALE 2.659f
#define SCI (LOGIT_SCALE / (127.0f * 127.0f))
#define BM 128
#define BN 128
#define BK 64                              // int8 elems per k-chunk (64 B/row)
#define NITER (DD / BK)                    // 8
#define NSTAGE 3

// ---- scratch (__device__ globals; no allocations allowed) ----
__device__ uint8_t g_imgQ[NN * DD];        // s8, normalized features x127
__device__ uint8_t g_txtQ[NN * DD];
__device__ float g_stats[4 * NN];          // [Zimg | Ztxt | Wimg | Wtxt]
__device__ int   g_cnt[100];
__device__ int   g_lab64;

// =============== helpers ===============
__device__ __forceinline__ uint32_t smem_u32(const void* p) {
    uint32_t a;
    asm("{ .reg .u64 t; cvta.to.shared.u64 t, %1; cvt.u32.u64 %0, t; }" : "=r"(a) : "l"(p));
    return a;
}
__device__ __forceinline__ void cp_async16(uint32_t s, const void* g) {
    uint64_t gg;
    asm("cvta.to.global.u64 %0, %1;" : "=l"(gg) : "l"(g));
    asm volatile("cp.async.cg.shared.global [%0], [%1], 16;" :: "r"(s), "l"(gg) : "memory");
}
#define CP_COMMIT() asm volatile("cp.async.commit_group;" ::: "memory")
#define CP_WAIT(n)  asm volatile("cp.async.wait_group %0;" :: "n"(n) : "memory")

__device__ __forceinline__ void ldsm_x4(uint32_t* r, uint32_t addr) {
    asm volatile("ldmatrix.sync.aligned.m8n8.x4.shared.b16 {%0,%1,%2,%3}, [%4];"
                 : "=r"(r[0]), "=r"(r[1]), "=r"(r[2]), "=r"(r[3]) : "r"(addr));
}
// int8 IMMA, m16n8k32, s32 accumulate (sm_80+ baseline feature)
__device__ __forceinline__ void mma_s8(int* d, const uint32_t* a, uint32_t b0, uint32_t b1) {
    asm volatile("mma.sync.aligned.m16n8k32.row.col.s32.s8.s8.s32 "
                 "{%0,%1,%2,%3}, {%4,%5,%6,%7}, {%8,%9}, {%0,%1,%2,%3};"
                 : "+r"(d[0]), "+r"(d[1]), "+r"(d[2]), "+r"(d[3])
                 : "r"(a[0]), "r"(a[1]), "r"(a[2]), "r"(a[3]), "r"(b0), "r"(b1));
}

// swizzled byte offset inside a [128 rows x 64B] stage (4 x 16B chunks per row)
__device__ __forceinline__ uint32_t sw_off(int row, int ch) {
    return (uint32_t)(row * 4 + (ch ^ ((row >> 1) & 3))) * 16u;
}

__device__ __forceinline__ int get_label(const int* __restrict__ labels, int i) {
    return g_lab64 ? labels[2 * i] : labels[i];
}

// ---------------- detect labels dtype + zero g_cnt + zero out ----------------
__global__ void detect_labels_kernel(const int* __restrict__ labels, float* __restrict__ out) {
    __shared__ int bad;
    const int t = threadIdx.x;
    if (t == 0) { bad = 0; out[0] = 0.0f; }
    if (t < 100) g_cnt[t] = 0;
    __syncthreads();
    int mybad = 0;
    for (int i = t; i < NN / 2; i += blockDim.x) {
        int lo = labels[2 * i];
        int hi = labels[2 * i + 1];
        if (hi != (lo < 0 ? -1 : 0)) mybad = 1;
    }
    if (mybad) bad = 1;
    __syncthreads();
    if (t == 0) g_lab64 = (bad == 0) ? 1 : 0;
}

// ---------------- normalize + fp32 -> s8(x127) + zero stats ----------------
__global__ void prep_kernel(const float* __restrict__ txt, const float* __restrict__ img) {
    const int row = blockIdx.x;
    const int t = threadIdx.x;
    const float* __restrict__ src = blockIdx.y ? txt : img;
    uint8_t* __restrict__ dst = blockIdx.y ? g_txtQ : g_imgQ;

    if (blockIdx.y == 0 && t < 4) g_stats[row * 4 + t] = 0.0f;

    float4 v = reinterpret_cast<const float4*>(src)[row * (DD / 4) + t];
    float ss = v.x * v.x + v.y * v.y + v.z * v.z + v.w * v.w;
#pragma unroll
    for (int m = 16; m; m >>= 1) ss += __shfl_xor_sync(0xffffffffu, ss, m);
    __shared__ float sm[4];
    if ((t & 31) == 0) sm[t >> 5] = ss;
    __syncthreads();
    float tot = sm[0] + sm[1] + sm[2] + sm[3];
    float inv = 127.0f / fmaxf(sqrtf(tot), 1e-12f);
    int q0 = max(-127, min(127, __float2int_rn(v.x * inv)));
    int q1 = max(-127, min(127, __float2int_rn(v.y * inv)));
    int q2 = max(-127, min(127, __float2int_rn(v.z * inv)));
    int q3 = max(-127, min(127, __float2int_rn(v.w * inv)));
    uint32_t pk = (uint32_t)(uint8_t)q0 | ((uint32_t)(uint8_t)q1 << 8) |
                  ((uint32_t)(uint8_t)q2 << 16) | ((uint32_t)(uint8_t)q3 << 24);
    reinterpret_cast<uint32_t*>(dst)[row * (DD / 4) + t] = pk;
}

// ---------------- INT8 IMMA GEMM + fused exp/mask statistics ----------------
// grid (64, 64), 256 threads (8 warps = 4M x 2N, warp tile 32x64).
__global__ __launch_bounds__(256) void gemm_mma_kernel(const int* __restrict__ labels) {
    __shared__ __align__(128) char As[NSTAGE][BM * 64];   // 3 x 8KB
    __shared__ __align__(128) char Bs[NSTAGE][BN * 64];
    __shared__ int labI[BM], labJ[BN];
    __shared__ float smRowZ[BM], smRowW[BM], smColZ[BN], smColW[BN];

    const int tid = threadIdx.x;
    const int wid = tid >> 5;
    const int lane = tid & 31;
    const int warpM = wid & 3;
    const int warpN = wid >> 2;
    const int iBase = blockIdx.y * BM;
    const int jBase = blockIdx.x * BN;

    if (tid < BM) {
        smRowZ[tid] = 0.f; smRowW[tid] = 0.f;
        smColZ[tid] = 0.f; smColW[tid] = 0.f;
        labI[tid] = get_label(labels, iBase + tid);
        labJ[tid] = get_label(labels, jBase + tid);
    }

    const uint8_t* __restrict__ gA = g_imgQ;
    const uint8_t* __restrict__ gB = g_txtQ;
    uint32_t aS[NSTAGE], bS[NSTAGE];
#pragma unroll
    for (int s = 0; s < NSTAGE; s++) { aS[s] = smem_u32(As[s]); bS[s] = smem_u32(Bs[s]); }

    // per-thread load coordinates hoisted out of the loop
    const int r0 = tid >> 2, c0 = tid & 3;
    const int r1 = (tid + 256) >> 2, c1 = (tid + 256) & 3;
    const uint32_t soA0 = sw_off(r0, c0), soA1 = sw_off(r1, c1);
    const uint8_t* pA0 = gA + (size_t)(iBase + r0) * DD + c0 * 16;
    const uint8_t* pA1 = gA + (size_t)(iBase + r1) * DD + c1 * 16;
    const uint8_t* pB0 = gB + (size_t)(jBase + r0) * DD + c0 * 16;
    const uint8_t* pB1 = gB + (size_t)(jBase + r1) * DD + c1 * 16;

    // prologue: issue stages 0 and 1
#pragma unroll
    for (int pre = 0; pre < 2; pre++) {
        const int kc = pre * BK;
        cp_async16(aS[pre] + soA0, pA0 + kc);
        cp_async16(aS[pre] + soA1, pA1 + kc);
        cp_async16(bS[pre] + soA0, pB0 + kc);
        cp_async16(bS[pre] + soA1, pB1 + kc);
        CP_COMMIT();
    }

    int acc[2][8][4];
#pragma unroll
    for (int mt = 0; mt < 2; mt++)
#pragma unroll
        for (int nt = 0; nt < 8; nt++)
#pragma unroll
            for (int f = 0; f < 4; f++) acc[mt][nt][f] = 0;

    for (int it = 0; it < NITER; it++) {
        CP_WAIT(1);
        __syncthreads();

        if (it + 2 < NITER) {
            const int kc = (it + 2) * BK;
            const int buf = (it + 2) % NSTAGE;
            cp_async16(aS[buf] + soA0, pA0 + kc);
            cp_async16(aS[buf] + soA1, pA1 + kc);
            cp_async16(bS[buf] + soA0, pB0 + kc);
            cp_async16(bS[buf] + soA1, pB1 + kc);
        }
        CP_COMMIT();

        const int buf = it % NSTAGE;
#pragma unroll
        for (int ks = 0; ks < 2; ks++) {   // two k=32 steps per 64B chunk
            uint32_t a[2][4], b[4][4];
            const int lrow = lane & 15;
            const int lch = ks * 2 + (lane >> 4);
#pragma unroll
            for (int mt = 0; mt < 2; mt++) {
                int row = warpM * 32 + mt * 16 + lrow;
                ldsm_x4(a[mt], aS[buf] + sw_off(row, lch));
            }
#pragma unroll
            for (int n2 = 0; n2 < 4; n2++) {
                int row = warpN * 64 + n2 * 16 + lrow;
                ldsm_x4(b[n2], bS[buf] + sw_off(row, lch));
            }
#pragma unroll
            for (int mt = 0; mt < 2; mt++)
#pragma unroll
                for (int nt = 0; nt < 8; nt++)
                    mma_s8(acc[mt][nt], a[mt], b[nt >> 1][nt & 1], b[nt >> 1][(nt & 1) + 2]);
        }
    }
    __syncthreads();

    // ---- fused epilogue ----
    const int g = lane >> 2;
    const int tc = (lane & 3) * 2;

    int li[2][2], gi[2][2], lj[8][2], gj[8][2];
#pragma unroll
    for (int mt = 0; mt < 2; mt++)
#pragma unroll
        for (int i = 0; i < 2; i++) {
            int r = warpM * 32 + mt * 16 + g + i * 8;
            gi[mt][i] = iBase + r;
            li[mt][i] = labI[r];
        }
#pragma unroll
    for (int nt = 0; nt < 8; nt++)
#pragma unroll
        for (int c = 0; c < 2; c++) {
            int cl = warpN * 64 + nt * 8 + tc + c;
            gj[nt][c] = cl;
            lj[nt][c] = labJ[cl];
        }

    float rowZ[2][2] = {}, rowW[2][2] = {}, colZ[8][2] = {};
#pragma unroll
    for (int mt = 0; mt < 2; mt++)
#pragma unroll
        for (int nt = 0; nt < 8; nt++)
#pragma unroll
            for (int f = 0; f < 4; f++) {
                int i = f >> 1, c = f & 1;
                float s = SCI * (float)acc[mt][nt][f];
                float e = __expf(s);
                rowZ[mt][i] += e;
                colZ[nt][c] += e;
                bool msk = (gi[mt][i] == jBase + gj[nt][c]) ||
                           ((li[mt][i] == lj[nt][c]) && (li[mt][i] != -1));
                if (msk) { rowW[mt][i] += s; atomicAdd(&smColW[gj[nt][c]], s); }
            }

#pragma unroll
    for (int mt = 0; mt < 2; mt++)
#pragma unroll
        for (int i = 0; i < 2; i++) {
#pragma unroll
            for (int m = 1; m <= 2; m <<= 1) {
                rowZ[mt][i] += __shfl_xor_sync(0xffffffffu, rowZ[mt][i], m);
                rowW[mt][i] += __shfl_xor_sync(0xffffffffu, rowW[mt][i], m);
            }
            if ((lane & 3) == 0) {
                int r = warpM * 32 + mt * 16 + g + i * 8;
                atomicAdd(&smRowZ[r], rowZ[mt][i]);
                atomicAdd(&smRowW[r], rowW[mt][i]);
            }
        }
#pragma unroll
    for (int nt = 0; nt < 8; nt++)
#pragma unroll
        for (int c = 0; c < 2; c++) {
#pragma unroll
            for (int m = 4; m <= 16; m <<= 1)
                colZ[nt][c] += __shfl_xor_sync(0xffffffffu, colZ[nt][c], m);
            if (lane < 4) atomicAdd(&smColZ[gj[nt][c]], colZ[nt][c]);
        }
    __syncthreads();

    if (tid < BM) {
        atomicAdd(&g_stats[iBase + tid],          smRowZ[tid]);
        atomicAdd(&g_stats[2 * NN + iBase + tid], smRowW[tid]);
        atomicAdd(&g_stats[NN + jBase + tid],     smColZ[tid]);
        atomicAdd(&g_stats[3 * NN + jBase + tid], smColW[tid]);
    }
}

// ---------------- label histogram (parallel) ----------------
__global__ void hist_kernel(const int* __restrict__ labels) {
    int i = blockIdx.x * blockDim.x + threadIdx.x;
    if (i < NN) {
        int l = get_label(labels, i);
        if (l >= 0) atomicAdd(&g_cnt[l], 1);
    }
}

// ---------------- final reduction -> scalar loss (parallel) ----------------
__global__ void reduce_kernel(const int* __restrict__ labels, float* __restrict__ out) {
    __shared__ float red[8];
    const int t = threadIdx.x;
    const int i = blockIdx.x * 256 + t;
    int l = get_label(labels, i);
    float invC = (l >= 0) ? (1.0f / (float)g_cnt[l]) : 1.0f;
    float acc = __logf(g_stats[i])      - g_stats[2 * NN + i] * invC
              + __logf(g_stats[NN + i]) - g_stats[3 * NN + i] * invC;
#pragma unroll
    for (int m = 16; m; m >>= 1) acc += __shfl_xor_sync(0xffffffffu, acc, m);
    if ((t & 31) == 0) red[t >> 5] = acc;
    __syncthreads();
    if (t < 32) {
        float v = (t < 8) ? red[t] : 0.f;
#pragma unroll
        for (int m = 4; m; m >>= 1) v += __shfl_xor_sync(0xffffffffu, v, m);
        if (t == 0) atomicAdd(out, v / (2.0f * NN));
    }
}

extern "C" void kernel_launch(void* const* d_in, const int* in_sizes, int n_in,
                              void* d_out, int out_size) {
    const float* txt = (const float*)d_in[0];
    const float* img = (const float*)d_in[1];
    const int* labels = (const int*)d_in[2];

    detect_labels_kernel<<<1, 1024>>>(labels, (float*)d_out);
    prep_kernel<<<dim3(NN, 2), 128>>>(txt, img);
    gemm_mma_kernel<<<dim3(NN / BN, NN / BM), 256>>>(labels);
    hist_kernel<<<NN / 256, 256>>>(labels);
    reduce_kernel<<<NN / 256, 256>>>(labels, (float*)d_out);
}

// round 8
// speedup vs baseline: 2.0776x; 2.0776x over previous
#include <cuda_runtime.h>
#include <cuda_fp16.h>
#include <stdint.h>

#define NN 8192
#define DD 512
#define LOGIT_SCALE 2.659f
#define FSCALE 32.0f
#define SC (LOGIT_SCALE / (FSCALE * FSCALE))
#define BM 128
#define BN 128
#define BK 64                              // fp8 elems per k-chunk (64 B/row)
#define NITER (DD / BK)                    // 8
#define NSTAGE 3

// ---- scratch (__device__ globals; no allocations allowed) ----
__device__ uint8_t g_imgQ[NN * DD];        // e4m3, normalized features x FSCALE
__device__ uint8_t g_txtQ[NN * DD];
__device__ float g_stats[4 * NN];          // [Zimg | Ztxt | Wimg | Wtxt]
__device__ int   g_cnt[100];
__device__ int   g_lab64;

// =============== helpers ===============
__device__ __forceinline__ uint32_t smem_u32(const void* p) {
    uint32_t a;
    asm("{ .reg .u64 t; cvta.to.shared.u64 t, %1; cvt.u32.u64 %0, t; }" : "=r"(a) : "l"(p));
    return a;
}
__device__ __forceinline__ void cp_async16(uint32_t s, const void* g) {
    uint64_t gg;
    asm("cvta.to.global.u64 %0, %1;" : "=l"(gg) : "l"(g));
    asm volatile("cp.async.cg.shared.global [%0], [%1], 16;" :: "r"(s), "l"(gg) : "memory");
}
#define CP_COMMIT() asm volatile("cp.async.commit_group;" ::: "memory")
#define CP_WAIT(n)  asm volatile("cp.async.wait_group %0;" :: "n"(n) : "memory")

__device__ __forceinline__ void ldsm_x4(uint32_t* r, uint32_t addr) {
    asm volatile("ldmatrix.sync.aligned.m8n8.x4.shared.b16 {%0,%1,%2,%3}, [%4];"
                 : "=r"(r[0]), "=r"(r[1]), "=r"(r[2]), "=r"(r[3]) : "r"(addr));
}
// fp8 e4m3 MMA, m16n8k32, **fp16 accumulate** (sm_89+): candidate 2x-rate path
__device__ __forceinline__ void mma_fp8_h(uint32_t* d, const uint32_t* a, uint32_t b0, uint32_t b1) {
    asm volatile("mma.sync.aligned.m16n8k32.row.col.f16.e4m3.e4m3.f16 "
                 "{%0,%1}, {%2,%3,%4,%5}, {%6,%7}, {%0,%1};"
                 : "+r"(d[0]), "+r"(d[1])
                 : "r"(a[0]), "r"(a[1]), "r"(a[2]), "r"(a[3]), "r"(b0), "r"(b1));
}
__device__ __forceinline__ uint16_t pack_e4m3x2(float lo, float hi) {
    uint16_t r;
    asm("cvt.rn.satfinite.e4m3x2.f32 %0, %2, %1;" : "=h"(r) : "f"(lo), "f"(hi));
    return r;
}

// swizzled byte offset inside a [128 rows x 64B] stage (4 x 16B chunks per row)
__device__ __forceinline__ uint32_t sw_off(int row, int ch) {
    return (uint32_t)(row * 4 + (ch ^ ((row >> 1) & 3))) * 16u;
}

__device__ __forceinline__ int get_label(const int* __restrict__ labels, int i) {
    return g_lab64 ? labels[2 * i] : labels[i];
}

// ---------------- detect labels dtype + zero g_cnt + zero out ----------------
__global__ void detect_labels_kernel(const int* __restrict__ labels, float* __restrict__ out) {
    __shared__ int bad;
    const int t = threadIdx.x;
    if (t == 0) { bad = 0; out[0] = 0.0f; }
    if (t < 100) g_cnt[t] = 0;
    __syncthreads();
    int mybad = 0;
    for (int i = t; i < NN / 2; i += blockDim.x) {
        int lo = labels[2 * i];
        int hi = labels[2 * i + 1];
        if (hi != (lo < 0 ? -1 : 0)) mybad = 1;
    }
    if (mybad) bad = 1;
    __syncthreads();
    if (t == 0) g_lab64 = (bad == 0) ? 1 : 0;
}

// ---------------- normalize + fp32 -> e4m3(xFSCALE) + zero stats ----------------
__global__ void prep_kernel(const float* __restrict__ txt, const float* __restrict__ img) {
    const int row = blockIdx.x;
    const int t = threadIdx.x;
    const float* __restrict__ src = blockIdx.y ? txt : img;
    uint8_t* __restrict__ dst = blockIdx.y ? g_txtQ : g_imgQ;

    if (blockIdx.y == 0 && t < 4) g_stats[row * 4 + t] = 0.0f;

    float4 v = reinterpret_cast<const float4*>(src)[row * (DD / 4) + t];
    float ss = v.x * v.x + v.y * v.y + v.z * v.z + v.w * v.w;
#pragma unroll
    for (int m = 16; m; m >>= 1) ss += __shfl_xor_sync(0xffffffffu, ss, m);
    __shared__ float sm[4];
    if ((t & 31) == 0) sm[t >> 5] = ss;
    __syncthreads();
    float tot = sm[0] + sm[1] + sm[2] + sm[3];
    float inv = FSCALE / fmaxf(sqrtf(tot), 1e-12f);
    uint16_t lo = pack_e4m3x2(v.x * inv, v.y * inv);
    uint16_t hi = pack_e4m3x2(v.z * inv, v.w * inv);
    reinterpret_cast<uint32_t*>(dst)[row * (DD / 4) + t] = (uint32_t)lo | ((uint32_t)hi << 16);
}

// ---------------- label histogram (parallel; independent of gemm) ----------------
__global__ void hist_kernel(const int* __restrict__ labels) {
    int i = blockIdx.x * blockDim.x + threadIdx.x;
    if (i < NN) {
        int l = get_label(labels, i);
        if (l >= 0) atomicAdd(&g_cnt[l], 1);
    }
}

// ---------------- FP8(f16-acc) QMMA GEMM + fused exp/mask statistics ----------------
// grid (64, 64), 256 threads (8 warps = 4M x 2N, warp tile 32x64).
__global__ __launch_bounds__(256) void gemm_mma_kernel(const int* __restrict__ labels) {
    __shared__ __align__(128) char As[NSTAGE][BM * 64];   // 3 x 8KB
    __shared__ __align__(128) char Bs[NSTAGE][BN * 64];
    __shared__ int labI[BM], labJ[BN];
    __shared__ float smRowZ[BM], smRowW[BM], smColZ[BN], smColW[BN];

    const int tid = threadIdx.x;
    const int wid = tid >> 5;
    const int lane = tid & 31;
    const int warpM = wid & 3;
    const int warpN = wid >> 2;
    const int iBase = blockIdx.y * BM;
    const int jBase = blockIdx.x * BN;

    if (tid < BM) {
        smRowZ[tid] = 0.f; smRowW[tid] = 0.f;
        smColZ[tid] = 0.f; smColW[tid] = 0.f;
        labI[tid] = get_label(labels, iBase + tid);
        labJ[tid] = get_label(labels, jBase + tid);
    }

    const uint8_t* __restrict__ gA = g_imgQ;
    const uint8_t* __restrict__ gB = g_txtQ;
    uint32_t aS[NSTAGE], bS[NSTAGE];
#pragma unroll
    for (int s = 0; s < NSTAGE; s++) { aS[s] = smem_u32(As[s]); bS[s] = smem_u32(Bs[s]); }

    const int r0 = tid >> 2, c0 = tid & 3;
    const int r1 = (tid + 256) >> 2, c1 = (tid + 256) & 3;
    const uint32_t soA0 = sw_off(r0, c0), soA1 = sw_off(r1, c1);
    const uint8_t* pA0 = gA + (size_t)(iBase + r0) * DD + c0 * 16;
    const uint8_t* pA1 = gA + (size_t)(iBase + r1) * DD + c1 * 16;
    const uint8_t* pB0 = gB + (size_t)(jBase + r0) * DD + c0 * 16;
    const uint8_t* pB1 = gB + (size_t)(jBase + r1) * DD + c1 * 16;

    // prologue: issue stages 0 and 1
#pragma unroll
    for (int pre = 0; pre < 2; pre++) {
        const int kc = pre * BK;
        cp_async16(aS[pre] + soA0, pA0 + kc);
        cp_async16(aS[pre] + soA1, pA1 + kc);
        cp_async16(bS[pre] + soA0, pB0 + kc);
        cp_async16(bS[pre] + soA1, pB1 + kc);
        CP_COMMIT();
    }

    uint32_t acc[2][8][2];                  // f16x2 pairs: [0]={r,c0|c1} [1]={r+8,c0|c1}
#pragma unroll
    for (int mt = 0; mt < 2; mt++)
#pragma unroll
        for (int nt = 0; nt < 8; nt++) { acc[mt][nt][0] = 0u; acc[mt][nt][1] = 0u; }

    for (int it = 0; it < NITER; it++) {
        CP_WAIT(1);
        __syncthreads();

        if (it + 2 < NITER) {
            const int kc = (it + 2) * BK;
            const int buf = (it + 2) % NSTAGE;
            cp_async16(aS[buf] + soA0, pA0 + kc);
            cp_async16(aS[buf] + soA1, pA1 + kc);
            cp_async16(bS[buf] + soA0, pB0 + kc);
            cp_async16(bS[buf] + soA1, pB1 + kc);
        }
        CP_COMMIT();

        const int buf = it % NSTAGE;
#pragma unroll
        for (int ks = 0; ks < 2; ks++) {   // two k=32 steps per 64B chunk
            uint32_t a[2][4], b[4][4];
            const int lrow = lane & 15;
            const int lch = ks * 2 + (lane >> 4);
#pragma unroll
            for (int mt = 0; mt < 2; mt++) {
                int row = warpM * 32 + mt * 16 + lrow;
                ldsm_x4(a[mt], aS[buf] + sw_off(row, lch));
            }
#pragma unroll
            for (int n2 = 0; n2 < 4; n2++) {
                int row = warpN * 64 + n2 * 16 + lrow;
                ldsm_x4(b[n2], bS[buf] + sw_off(row, lch));
            }
#pragma unroll
            for (int mt = 0; mt < 2; mt++)
#pragma unroll
                for (int nt = 0; nt < 8; nt++)
                    mma_fp8_h(acc[mt][nt], a[mt], b[nt >> 1][nt & 1], b[nt >> 1][(nt & 1) + 2]);
        }
    }
    __syncthreads();

    // ---- fused epilogue ----
    const int g = lane >> 2;
    const int tc = (lane & 3) * 2;

    int li[2][2], gi[2][2], lj[8][2], gj[8][2];
#pragma unroll
    for (int mt = 0; mt < 2; mt++)
#pragma unroll
        for (int i = 0; i < 2; i++) {
            int r = warpM * 32 + mt * 16 + g + i * 8;
            gi[mt][i] = iBase + r;
            li[mt][i] = labI[r];
        }
#pragma unroll
    for (int nt = 0; nt < 8; nt++)
#pragma unroll
        for (int c = 0; c < 2; c++) {
            int cl = warpN * 64 + nt * 8 + tc + c;
            gj[nt][c] = cl;
            lj[nt][c] = labJ[cl];
        }

    float rowZ[2][2] = {}, rowW[2][2] = {}, colZ[8][2] = {};
#pragma unroll
    for (int mt = 0; mt < 2; mt++)
#pragma unroll
        for (int nt = 0; nt < 8; nt++)
#pragma unroll
            for (int i = 0; i < 2; i++) {       // i: row half (g, g+8)
                float2 p = __half22float2(*reinterpret_cast<const __half2*>(&acc[mt][nt][i]));
#pragma unroll
                for (int c = 0; c < 2; c++) {   // c: col within pair
                    float s = SC * (c ? p.y : p.x);
                    float e = __expf(s);
                    rowZ[mt][i] += e;
                    colZ[nt][c] += e;
                    bool msk = (gi[mt][i] == jBase + gj[nt][c]) ||
                               ((li[mt][i] == lj[nt][c]) && (li[mt][i] != -1));
                    if (msk) { rowW[mt][i] += s; atomicAdd(&smColW[gj[nt][c]], s); }
                }
            }

#pragma unroll
    for (int mt = 0; mt < 2; mt++)
#pragma unroll
        for (int i = 0; i < 2; i++) {
#pragma unroll
            for (int m = 1; m <= 2; m <<= 1) {
                rowZ[mt][i] += __shfl_xor_sync(0xffffffffu, rowZ[mt][i], m);
                rowW[mt][i] += __shfl_xor_sync(0xffffffffu, rowW[mt][i], m);
            }
            if ((lane & 3) == 0) {
                int r = warpM * 32 + mt * 16 + g + i * 8;
                atomicAdd(&smRowZ[r], rowZ[mt][i]);
                atomicAdd(&smRowW[r], rowW[mt][i]);
            }
        }
#pragma unroll
    for (int nt = 0; nt < 8; nt++)
#pragma unroll
        for (int c = 0; c < 2; c++) {
#pragma unroll
            for (int m = 4; m <= 16; m <<= 1)
                colZ[nt][c] += __shfl_xor_sync(0xffffffffu, colZ[nt][c], m);
            if (lane < 4) atomicAdd(&smColZ[gj[nt][c]], colZ[nt][c]);
        }
    __syncthreads();

    if (tid < BM) {
        atomicAdd(&g_stats[iBase + tid],          smRowZ[tid]);
        atomicAdd(&g_stats[2 * NN + iBase + tid], smRowW[tid]);
        atomicAdd(&g_stats[NN + jBase + tid],     smColZ[tid]);
        atomicAdd(&g_stats[3 * NN + jBase + tid], smColW[tid]);
    }
}

// ---------------- final reduction -> scalar loss (parallel) ----------------
__global__ void reduce_kernel(const int* __restrict__ labels, float* __restrict__ out) {
    __shared__ float red[8];
    const int t = threadIdx.x;
    const int i = blockIdx.x * 256 + t;
    int l = get_label(labels, i);
    float invC = (l >= 0) ? (1.0f / (float)g_cnt[l]) : 1.0f;
    float acc = __logf(g_stats[i])      - g_stats[2 * NN + i] * invC
              + __logf(g_stats[NN + i]) - g_stats[3 * NN + i] * invC;
#pragma unroll
    for (int m = 16; m; m >>= 1) acc += __shfl_xor_sync(0xffffffffu, acc, m);
    if ((t & 31) == 0) red[t >> 5] = acc;
    __syncthreads();
    if (t < 32) {
        float v = (t < 8) ? red[t] : 0.f;
#pragma unroll
        for (int m = 4; m; m >>= 1) v += __shfl_xor_sync(0xffffffffu, v, m);
        if (t == 0) atomicAdd(out, v / (2.0f * NN));
    }
}

extern "C" void kernel_launch(void* const* d_in, const int* in_sizes, int n_in,
                              void* d_out, int out_size) {
    const float* txt = (const float*)d_in[0];
    const float* img = (const float*)d_in[1];
    const int* labels = (const int*)d_in[2];

    detect_labels_kernel<<<1, 1024>>>(labels, (float*)d_out);
    prep_kernel<<<dim3(NN, 2), 128>>>(txt, img);
    hist_kernel<<<NN / 256, 256>>>(labels);                       // launch idx 2
    gemm_mma_kernel<<<dim3(NN / BN, NN / BM), 256>>>(labels);     // launch idx 3 -> ncu target
    reduce_kernel<<<NN / 256, 256>>>(labels, (float*)d_out);
}